// round 8
// baseline (speedup 1.0000x reference)
#include <cuda_runtime.h>
#include <cstdint>

// input : 2 tensors float32 [2048, 8, 8, 64]  (re, im)   8,388,608 elems each
// output: float32 [2, 2048, 8, 16, 64]                  33,554,432 elems
//
// Per block b (qubit q = 0 if b even else 5; mask m = 32 or 1):
//   top (d 0..7):  out[i] = S * in[i ^ m],              S = 2^-0.25
//   bot (d 8..15): out_re[i] = sgn * A * (re[i]-im[i])
//                  out_im[i] = sgn * A * (re[i]+im[i]), A = 2^-0.75,
//                  sgn = (i & m) ? -1 : +1
//
// Double-buffered TMA bulk stores: each CTA produces TWO 16KB-per-part tiles.
// Tile 0's cp.async.bulk store drains while tile 1 is computed; single wait
// at kernel end. Store path bypasses L1/LSU, DRAM sees 16KB bursts.

#define S_CONST 0.8408964152537145f   // 2^-0.25
#define A_CONST 0.5946035575013605f   // 2^-0.75

__device__ __forceinline__ float4 scale4(float4 v, float s) {
    return make_float4(s * v.x, s * v.y, s * v.z, s * v.w);
}
__device__ __forceinline__ float4 swap_scale4(float4 v, float s) {
    return make_float4(s * v.y, s * v.x, s * v.w, s * v.z);
}
__device__ __forceinline__ uint32_t smem_u32(const void* p) {
    return (uint32_t)__cvta_generic_to_shared(p);
}

__global__ void __launch_bounds__(256)
entangle_db_kernel(const float4* __restrict__ re4,
                   const float4* __restrict__ im4,
                   float* __restrict__ out,
                   int n_ctas)
{
    // two buffers, each: [4 bblk][16 rows][16 float4] per part = 16KB/part
    __shared__ float4 s_re[2][4 * 16 * 16];
    __shared__ float4 s_im[2][4 * 16 * 16];

    int cta = blockIdx.x;
    if (cta >= n_ctas) return;
    int tid = threadIdx.x;

    // decode within tile: tid = ((bb_local*8 + d)*8 + i8)
    int i8  = tid & 7;            // low float4 index; partner at i8+8
    int d   = (tid >> 3) & 7;
    int bbl = (tid >> 6) & 3;     // local bblk 0..3

    const int PS = 2048 * 8 * 16 * 64;           // 16,777,216 floats (imag offset)

    #pragma unroll
    for (int stage = 0; stage < 2; stage++) {
        int grp  = (cta << 1) + stage;           // tile index, 0..4095
        int bblk = (grp << 2) + bbl;             // global b*8+blk
        int blk  = bblk & 7;
        const bool even_blk = (blk & 1) == 0;    // qubit 0 (m=32) vs 5 (m=1)

        int f_lo = (bblk << 7) + (d << 4) + i8;
        int f_hi = f_lo + 8;

        float4 r_lo = re4[f_lo];
        float4 r_hi = re4[f_hi];
        float4 m_lo = im4[f_lo];
        float4 m_hi = im4[f_hi];

        float4 tr_lo, tr_hi, ti_lo, ti_hi;   // top (X gate)
        float4 br_lo, br_hi, bi_lo, bi_hi;   // bot (Z gate)

        if (even_blk) {
            tr_lo = scale4(r_hi, S_CONST);  ti_lo = scale4(m_hi, S_CONST);
            tr_hi = scale4(r_lo, S_CONST);  ti_hi = scale4(m_lo, S_CONST);
            br_lo = make_float4( A_CONST * (r_lo.x - m_lo.x),  A_CONST * (r_lo.y - m_lo.y),
                                 A_CONST * (r_lo.z - m_lo.z),  A_CONST * (r_lo.w - m_lo.w));
            bi_lo = make_float4( A_CONST * (r_lo.x + m_lo.x),  A_CONST * (r_lo.y + m_lo.y),
                                 A_CONST * (r_lo.z + m_lo.z),  A_CONST * (r_lo.w + m_lo.w));
            br_hi = make_float4(-A_CONST * (r_hi.x - m_hi.x), -A_CONST * (r_hi.y - m_hi.y),
                                -A_CONST * (r_hi.z - m_hi.z), -A_CONST * (r_hi.w - m_hi.w));
            bi_hi = make_float4(-A_CONST * (r_hi.x + m_hi.x), -A_CONST * (r_hi.y + m_hi.y),
                                -A_CONST * (r_hi.z + m_hi.z), -A_CONST * (r_hi.w + m_hi.w));
        } else {
            tr_lo = swap_scale4(r_lo, S_CONST);  ti_lo = swap_scale4(m_lo, S_CONST);
            tr_hi = swap_scale4(r_hi, S_CONST);  ti_hi = swap_scale4(m_hi, S_CONST);
            br_lo = make_float4( A_CONST * (r_lo.x - m_lo.x), -A_CONST * (r_lo.y - m_lo.y),
                                 A_CONST * (r_lo.z - m_lo.z), -A_CONST * (r_lo.w - m_lo.w));
            bi_lo = make_float4( A_CONST * (r_lo.x + m_lo.x), -A_CONST * (r_lo.y + m_lo.y),
                                 A_CONST * (r_lo.z + m_lo.z), -A_CONST * (r_lo.w + m_lo.w));
            br_hi = make_float4( A_CONST * (r_hi.x - m_hi.x), -A_CONST * (r_hi.y - m_hi.y),
                                 A_CONST * (r_hi.z - m_hi.z), -A_CONST * (r_hi.w - m_hi.w));
            bi_hi = make_float4( A_CONST * (r_hi.x + m_hi.x), -A_CONST * (r_hi.y + m_hi.y),
                                 A_CONST * (r_hi.z + m_hi.z), -A_CONST * (r_hi.w + m_hi.w));
        }

        // SMEM image mirrors gmem: [bbl][row 0..15][i4 0..15]
        int st = (bbl << 8) + (d << 4) + i8;    // top row d
        int sb = st + (8 << 4);                 // bot row d+8
        s_re[stage][st]     = tr_lo;
        s_re[stage][st + 8] = tr_hi;
        s_re[stage][sb]     = br_lo;
        s_re[stage][sb + 8] = br_hi;
        s_im[stage][st]     = ti_lo;
        s_im[stage][st + 8] = ti_hi;
        s_im[stage][sb]     = bi_lo;
        s_im[stage][sb + 8] = bi_hi;

        __syncthreads();
        asm volatile("fence.proxy.async.shared::cta;" ::: "memory");

        if (tid == 0) {
            float* g_re = out + (size_t)grp * 4096;   // 4 bblk * 16*64 floats
            float* g_im = g_re + PS;
            uint32_t sre = smem_u32(s_re[stage]);
            uint32_t sim = smem_u32(s_im[stage]);
            asm volatile("cp.async.bulk.global.shared::cta.bulk_group [%0], [%1], %2;"
                         :: "l"(g_re), "r"(sre), "n"(16384) : "memory");
            asm volatile("cp.async.bulk.global.shared::cta.bulk_group [%0], [%1], %2;"
                         :: "l"(g_im), "r"(sim), "n"(16384) : "memory");
            asm volatile("cp.async.bulk.commit_group;" ::: "memory");
        }
        // no wait here: stage 1 uses different SMEM buffers, so stage 0's
        // store drains while stage 1 computes
    }

    // single wait at the end (only tid 0 issued the copies)
    if (tid == 0) {
        asm volatile("cp.async.bulk.wait_group 0;" ::: "memory");
    }
}

extern "C" void kernel_launch(void* const* d_in, const int* in_sizes, int n_in,
                              void* d_out, int out_size)
{
    const float4* re4 = (const float4*)d_in[0];
    const float4* im4 = (const float4*)d_in[1];
    float* out        = (float*)d_out;

    int n_pairs = in_sizes[0] / 8;        // 1,048,576
    int n_ctas  = n_pairs / 512;          // 2048 CTAs, 2 tiles each
    entangle_db_kernel<<<n_ctas, 256>>>(re4, im4, out, n_ctas);
}